// round 3
// baseline (speedup 1.0000x reference)
#include <cuda_runtime.h>
#include <cstdint>

#define N_NODES 50000
#define EMB 128
#define NRBF 20

// Scratch (static device arrays are allowed; runtime alloc is not)
__device__ float g_h[(size_t)N_NODES * EMB];         // silu(s@W1+b1)
__device__ float g_spass[(size_t)N_NODES * 3 * EMB]; // h@W2+b2

// ---------- f32x2 helpers ----------
__device__ __forceinline__ unsigned long long fma2(unsigned long long a,
                                                   unsigned long long b,
                                                   unsigned long long c) {
    unsigned long long d;
    asm("fma.rn.f32x2 %0, %1, %2, %3;" : "=l"(d) : "l"(a), "l"(b), "l"(c));
    return d;
}
__device__ __forceinline__ unsigned long long dup2(float a) {
    unsigned long long r;
    asm("mov.b64 %0, {%1, %1};" : "=l"(r) : "f"(a));
    return r;
}
__device__ __forceinline__ unsigned long long packf(float lo, float hi) {
    unsigned long long r;
    asm("mov.b64 %0, {%1, %2};" : "=l"(r) : "f"(lo), "f"(hi));
    return r;
}
__device__ __forceinline__ float lof(unsigned long long v) {
    return __uint_as_float((unsigned)(v & 0xffffffffull));
}
__device__ __forceinline__ float hif(unsigned long long v) {
    return __uint_as_float((unsigned)(v >> 32));
}

// ---------- GEMM core: C[M x N] = act(A[M x 128] @ W[128 x N] + b) ----------
// block: 128 threads, M_TILE = 64 rows. thread t: row m = t & 63, col-half nh = t >> 6.
// N processed in chunks of 16 columns; each thread owns 8 of them.
template <int N, int ACT>
__device__ __forceinline__ void gemm_bias_body(
    const float* __restrict__ A, const float* __restrict__ W,
    const float* __restrict__ bias, float* __restrict__ C, int M)
{
    __shared__ __align__(16) float A_sh[64 * 129];
    __shared__ __align__(16) float W_sh[128 * 16];

    const int t = threadIdx.x;
    const int m0 = blockIdx.x * 64;

    // Stage A tile (64 x 128), coalesced global reads
    for (int lin = t; lin < 64 * 128; lin += 128) {
        int m = lin >> 7;
        int k = lin & 127;
        float val = (m0 + m < M) ? A[(size_t)(m0 + m) * 128 + k] : 0.f;
        A_sh[m * 129 + k] = val;
    }
    __syncthreads();

    const int m = t & 63;
    const int nh = t >> 6;               // 0 or 1
    const bool valid = (m0 + m) < M;
    const float* arow = A_sh + m * 129;

    for (int n0 = 0; n0 < N; n0 += 16) {
        // Stage W chunk: thread t handles k = t, 16 floats
        {
            const float4* srcp = (const float4*)(W + (size_t)t * N + n0);
            float4* dstp = (float4*)(W_sh + t * 16);
            dstp[0] = srcp[0]; dstp[1] = srcp[1];
            dstp[2] = srcp[2]; dstp[3] = srcp[3];
        }
        __syncthreads();

        unsigned long long acc[4] = {0ull, 0ull, 0ull, 0ull};
        #pragma unroll 16
        for (int k = 0; k < 128; k++) {
            float a = arow[k];
            unsigned long long a2 = dup2(a);
            const ulonglong2* wrow = (const ulonglong2*)(W_sh + k * 16 + nh * 8);
            ulonglong2 wA = wrow[0];
            ulonglong2 wB = wrow[1];
            acc[0] = fma2(a2, wA.x, acc[0]);
            acc[1] = fma2(a2, wA.y, acc[1]);
            acc[2] = fma2(a2, wB.x, acc[2]);
            acc[3] = fma2(a2, wB.y, acc[3]);
        }

        // epilogue: bias (+ optional silu), store 8 floats
        float c[8];
        #pragma unroll
        for (int p = 0; p < 4; p++) {
            c[2 * p]     = lof(acc[p]);
            c[2 * p + 1] = hif(acc[p]);
        }
        const int ncol = n0 + nh * 8;
        #pragma unroll
        for (int j = 0; j < 8; j++) {
            float x = c[j] + bias[ncol + j];
            if (ACT) {
                x = x / (1.0f + __expf(-x));  // silu
            }
            c[j] = x;
        }
        if (valid) {
            float4* outp = (float4*)(C + (size_t)(m0 + m) * N + ncol);
            outp[0] = make_float4(c[0], c[1], c[2], c[3]);
            outp[1] = make_float4(c[4], c[5], c[6], c[7]);
        }
        __syncthreads();  // protect W_sh before next chunk
    }
}

__global__ __launch_bounds__(128) void gemm1_kernel(
    const float* __restrict__ A, const float* __restrict__ W,
    const float* __restrict__ bias, int M)
{
    gemm_bias_body<128, 1>(A, W, bias, g_h, M);
}

__global__ __launch_bounds__(128) void gemm2_kernel(
    const float* __restrict__ W, const float* __restrict__ bias, int M)
{
    gemm_bias_body<384, 0>(g_h, W, bias, g_spass, M);
}

// ---------- Edge kernel ----------
// block: 128 threads, one chunk of 128 edges per block.
// thread t owns output columns t (delta_v_g), t+128 (delta_s), t+256 (delta_rep).
// Wr columns held in registers, pre-packed in f32x2 pairs over the RBF index.
__global__ __launch_bounds__(128) void edge_kernel(
    const int* __restrict__ edges,         // [E][2] int32 pairs
    const float* __restrict__ r_ij,        // [E]
    const float* __restrict__ rnorm,       // [E][3]
    const float* __restrict__ Wr,          // [20][384]
    const float* __restrict__ br,          // [384]
    const float* __restrict__ v_in,        // [N][3][128]
    float* __restrict__ s_out,             // [N][128]
    float* __restrict__ v_out,             // [N][3][128]
    int n_edges)
{
    __shared__ __align__(16) float rb_sh[128][24];  // 20 rbf, fc, rn0..rn2 (row = 96B)
    __shared__ int src_sh[128];
    __shared__ int dst_sh[128];

    const int t = threadIdx.x;
    const int base = blockIdx.x * 128;

    // Preload Wr columns (packed pairs over n) + bias
    unsigned long long wrP0[10], wrP1[10], wrP2[10];
    #pragma unroll
    for (int p = 0; p < 10; p++) {
        wrP0[p] = packf(Wr[(2 * p) * 384 + t],       Wr[(2 * p + 1) * 384 + t]);
        wrP1[p] = packf(Wr[(2 * p) * 384 + 128 + t], Wr[(2 * p + 1) * 384 + 128 + t]);
        wrP2[p] = packf(Wr[(2 * p) * 384 + 256 + t], Wr[(2 * p + 1) * 384 + 256 + t]);
    }
    const float br0 = br[t], br1 = br[128 + t], br2 = br[256 + t];

    // Phase 1: thread t computes edge (base+t)'s rbf / fcut / scalars
    const int e_my = base + t;
    if (e_my < n_edges) {
        int2 ed = ((const int2*)edges)[e_my];
        src_sh[t] = ed.x;
        dst_sh[t] = ed.y;
        float r = r_ij[e_my];
        float inv_r = 1.0f / r;
        float q = r * 0.2f;  // r / R_CUT
        #pragma unroll
        for (int n = 1; n <= NRBF; n++) {
            rb_sh[t][n - 1] = sinpif((float)n * q) * inv_r;
        }
        float fc = (r <= 5.0f) ? 0.5f * (cospif(q) + 1.0f) : 0.0f;
        rb_sh[t][20] = fc;
        rb_sh[t][21] = rnorm[3 * e_my + 0];
        rb_sh[t][22] = rnorm[3 * e_my + 1];
        rb_sh[t][23] = rnorm[3 * e_my + 2];
    }
    __syncthreads();

    const int cnt = min(128, n_edges - base);
    for (int e = 0; e < cnt; e++) {
        const int src = src_sh[e];
        const int dst = dst_sh[e];
        const float* row = rb_sh[e];

        unsigned long long a0 = 0ull, a1 = 0ull, a2 = 0ull;
        #pragma unroll
        for (int p = 0; p < 5; p++) {
            ulonglong2 rp = ((const ulonglong2*)row)[p];  // rbf[4p..4p+3] as 2 pairs
            a0 = fma2(rp.x, wrP0[2 * p], a0);
            a0 = fma2(rp.y, wrP0[2 * p + 1], a0);
            a1 = fma2(rp.x, wrP1[2 * p], a1);
            a1 = fma2(rp.y, wrP1[2 * p + 1], a1);
            a2 = fma2(rp.x, wrP2[2 * p], a2);
            a2 = fma2(rp.y, wrP2[2 * p + 1], a2);
        }
        const float fc  = row[20];
        const float rn0 = row[21], rn1 = row[22], rn2 = row[23];

        float g   = (lof(a0) + hif(a0) + br0) * fc;
        float ds  = (lof(a1) + hif(a1) + br1) * fc;
        float rep = (lof(a2) + hif(a2) + br2) * fc;

        const float* sp = g_spass + (size_t)dst * 384 + t;
        g   *= sp[0];
        ds  *= sp[128];
        rep *= sp[256];

        atomicAdd(s_out + (size_t)src * 128 + t, ds);

        const float* vp = v_in + (size_t)dst * 384 + t;
        float* vo = v_out + (size_t)src * 384 + t;
        atomicAdd(vo,       fmaf(vp[0],   g, rn0 * rep));
        atomicAdd(vo + 128, fmaf(vp[128], g, rn1 * rep));
        atomicAdd(vo + 256, fmaf(vp[256], g, rn2 * rep));
    }
}

// ---------- launch ----------
extern "C" void kernel_launch(void* const* d_in, const int* in_sizes, int n_in,
                              void* d_out, int out_size)
{
    const float* s     = (const float*)d_in[0];
    const float* v     = (const float*)d_in[1];
    const int*   edges = (const int*)d_in[2];
    const float* r_ij  = (const float*)d_in[3];
    const float* rnorm = (const float*)d_in[4];
    const float* W1    = (const float*)d_in[5];
    const float* b1    = (const float*)d_in[6];
    const float* W2    = (const float*)d_in[7];
    const float* b2    = (const float*)d_in[8];
    const float* Wr    = (const float*)d_in[9];
    const float* br    = (const float*)d_in[10];

    const int n_nodes = in_sizes[0] / EMB;
    const int n_edges = in_sizes[2] / 2;

    float* s_out = (float*)d_out;
    float* v_out = s_out + (size_t)n_nodes * EMB;

    // init outputs: s_out = s, v_out = v (capturable async D2D copies)
    cudaMemcpyAsync(s_out, s, (size_t)n_nodes * EMB * sizeof(float),
                    cudaMemcpyDeviceToDevice, 0);
    cudaMemcpyAsync(v_out, v, (size_t)n_nodes * 3 * EMB * sizeof(float),
                    cudaMemcpyDeviceToDevice, 0);

    const int gemm_blocks = (n_nodes + 63) / 64;
    gemm1_kernel<<<gemm_blocks, 128>>>(s, W1, b1, n_nodes);
    gemm2_kernel<<<gemm_blocks, 128>>>(W2, b2, n_nodes);

    const int edge_blocks = (n_edges + 127) / 128;
    edge_kernel<<<edge_blocks, 128>>>(edges, r_ij, rnorm, Wr, br,
                                      v, s_out, v_out, n_edges);
}

// round 4
// speedup vs baseline: 1.2481x; 1.2481x over previous
#include <cuda_runtime.h>
#include <cstdint>

#define N_NODES 50000
#define EMB 128
#define NRBF 20

// Scratch (static device arrays are allowed; runtime alloc is not)
__device__ float g_h[(size_t)N_NODES * EMB];         // silu(s@W1+b1)
__device__ float g_spass[(size_t)N_NODES * 3 * EMB]; // h@W2+b2

// ---------- f32x2 helpers ----------
__device__ __forceinline__ unsigned long long fma2(unsigned long long a,
                                                   unsigned long long b,
                                                   unsigned long long c) {
    unsigned long long d;
    asm("fma.rn.f32x2 %0, %1, %2, %3;" : "=l"(d) : "l"(a), "l"(b), "l"(c));
    return d;
}
__device__ __forceinline__ unsigned long long dup2(float a) {
    unsigned long long r;
    asm("mov.b64 %0, {%1, %1};" : "=l"(r) : "f"(a));
    return r;
}
__device__ __forceinline__ unsigned long long packf(float lo, float hi) {
    unsigned long long r;
    asm("mov.b64 %0, {%1, %2};" : "=l"(r) : "f"(lo), "f"(hi));
    return r;
}
__device__ __forceinline__ float lof(unsigned long long v) {
    return __uint_as_float((unsigned)(v & 0xffffffffull));
}
__device__ __forceinline__ float hif(unsigned long long v) {
    return __uint_as_float((unsigned)(v >> 32));
}

// ---------- 8x8 register-blocked GEMM ----------
// C[M x N] = act(A[M x 128] @ W[128 x N] + b)
// Block: 128 threads. Tile: 128 rows x 64-col chunks.
// Thread t: rg = t>>3 (16 rowgroups of 8 rows), cg = t&7 (8 colgroups of 8 cols).
// Per k: 8 LDS.32 (a, conflict-free), 2 LDS.128 (w, broadcast), 32 FFMA2.
// A_sh: [128][129] row-major (pad 129). W_sh: [128][64].
#define AS_STRIDE 129
#define GEMM_SMEM_BYTES ((128 * AS_STRIDE + 128 * 64) * 4)

template <int N, int ACT>
__device__ __forceinline__ void gemm8x8_body(
    const float* __restrict__ A, const float* __restrict__ W,
    const float* __restrict__ bias, float* __restrict__ C, int M)
{
    extern __shared__ __align__(16) float smem[];
    float* A_sh = smem;                    // 128 * 129
    float* W_sh = smem + 128 * AS_STRIDE;  // 128 * 64

    const int t = threadIdx.x;
    const int cg = t & 7;
    const int rg = t >> 3;

    for (int m0 = blockIdx.x * 128; m0 < M; m0 += gridDim.x * 128) {
        // ---- stage A tile (128 x 128): coalesced reads, conflict-free writes
        for (int lin = t; lin < 128 * 128; lin += 128) {
            int m = lin >> 7;
            int k = lin & 127;
            float val = (m0 + m < M) ? A[(size_t)(m0 + m) * 128 + k] : 0.f;
            A_sh[m * AS_STRIDE + k] = val;
        }
        __syncthreads();

        for (int n0 = 0; n0 < N; n0 += 64) {
            // ---- stage W chunk (128 x 64) as float4, minimal-phase STS
            for (int idx = t; idx < 128 * 16; idx += 128) {
                int k = idx >> 4;
                int j = idx & 15;
                ((float4*)(W_sh + k * 64))[j] =
                    ((const float4*)(W + (size_t)k * N + n0))[j];
            }
            __syncthreads();

            unsigned long long acc[8][4];
            #pragma unroll
            for (int i = 0; i < 8; i++)
                #pragma unroll
                for (int j = 0; j < 4; j++) acc[i][j] = 0ull;

            const float* arow = A_sh + rg * 8 * AS_STRIDE;
            const float* wcol = W_sh + cg * 8;

            #pragma unroll 4
            for (int k = 0; k < 128; k++) {
                ulonglong2 wA = *(const ulonglong2*)(wcol + k * 64);
                ulonglong2 wB = *(const ulonglong2*)(wcol + k * 64 + 4);
                #pragma unroll
                for (int i = 0; i < 8; i++) {
                    unsigned long long a2 = dup2(arow[i * AS_STRIDE + k]);
                    acc[i][0] = fma2(a2, wA.x, acc[i][0]);
                    acc[i][1] = fma2(a2, wA.y, acc[i][1]);
                    acc[i][2] = fma2(a2, wB.x, acc[i][2]);
                    acc[i][3] = fma2(a2, wB.y, acc[i][3]);
                }
            }

            // ---- epilogue
            const int ncol = n0 + cg * 8;
            float bb[8];
            #pragma unroll
            for (int j = 0; j < 8; j++) bb[j] = bias[ncol + j];

            #pragma unroll
            for (int i = 0; i < 8; i++) {
                const int m = m0 + rg * 8 + i;
                if (m < M) {
                    float c[8];
                    #pragma unroll
                    for (int j = 0; j < 4; j++) {
                        c[2 * j]     = lof(acc[i][j]) + bb[2 * j];
                        c[2 * j + 1] = hif(acc[i][j]) + bb[2 * j + 1];
                    }
                    if (ACT) {
                        #pragma unroll
                        for (int j = 0; j < 8; j++)
                            c[j] = c[j] / (1.0f + __expf(-c[j]));  // silu
                    }
                    float4* outp = (float4*)(C + (size_t)m * N + ncol);
                    outp[0] = make_float4(c[0], c[1], c[2], c[3]);
                    outp[1] = make_float4(c[4], c[5], c[6], c[7]);
                }
            }
            __syncthreads();  // protect W_sh (and A_sh before restage)
        }
    }
}

__global__ __launch_bounds__(128) void gemm1_kernel(
    const float* __restrict__ A, const float* __restrict__ W,
    const float* __restrict__ bias, int M)
{
    gemm8x8_body<128, 1>(A, W, bias, g_h, M);
}

__global__ __launch_bounds__(128) void gemm2_kernel(
    const float* __restrict__ W, const float* __restrict__ bias, int M)
{
    gemm8x8_body<384, 0>(g_h, W, bias, g_spass, M);
}

// ---------- Edge kernel ----------
// block: 128 threads, one chunk of 128 edges per block.
// thread t owns output columns t (delta_v_g), t+128 (delta_s), t+256 (delta_rep).
// Wr columns held in registers, packed f32x2 pairs over the RBF index.
// Gathers for edge e+1 issued before edge e's dot product (latency cover).
__global__ __launch_bounds__(128) void edge_kernel(
    const int* __restrict__ edges,         // [E][2] int32 pairs
    const float* __restrict__ r_ij,        // [E]
    const float* __restrict__ rnorm,       // [E][3]
    const float* __restrict__ Wr,          // [20][384]
    const float* __restrict__ br,          // [384]
    const float* __restrict__ v_in,        // [N][3][128]
    float* __restrict__ s_out,             // [N][128]
    float* __restrict__ v_out,             // [N][3][128]
    int n_edges)
{
    __shared__ __align__(16) float rb_sh[128][24];  // 20 rbf, fc, rn0..rn2
    __shared__ int src_sh[128];
    __shared__ int dst_sh[128];

    const int t = threadIdx.x;
    const int base = blockIdx.x * 128;

    // Preload Wr columns (packed pairs over n) + bias
    unsigned long long wrP0[10], wrP1[10], wrP2[10];
    #pragma unroll
    for (int p = 0; p < 10; p++) {
        wrP0[p] = packf(Wr[(2 * p) * 384 + t],       Wr[(2 * p + 1) * 384 + t]);
        wrP1[p] = packf(Wr[(2 * p) * 384 + 128 + t], Wr[(2 * p + 1) * 384 + 128 + t]);
        wrP2[p] = packf(Wr[(2 * p) * 384 + 256 + t], Wr[(2 * p + 1) * 384 + 256 + t]);
    }
    const float br0 = br[t], br1 = br[128 + t], br2 = br[256 + t];

    // Phase 1: thread t computes edge (base+t)'s rbf / fcut / geometry
    const int e_my = base + t;
    if (e_my < n_edges) {
        int2 ed = ((const int2*)edges)[e_my];
        src_sh[t] = ed.x;
        dst_sh[t] = ed.y;
        float r = r_ij[e_my];
        float inv_r = 1.0f / r;
        float q = r * 0.2f;  // r / R_CUT
        #pragma unroll
        for (int n = 1; n <= NRBF; n++) {
            rb_sh[t][n - 1] = sinpif((float)n * q) * inv_r;
        }
        float fc = (r <= 5.0f) ? 0.5f * (cospif(q) + 1.0f) : 0.0f;
        rb_sh[t][20] = fc;
        rb_sh[t][21] = rnorm[3 * e_my + 0];
        rb_sh[t][22] = rnorm[3 * e_my + 1];
        rb_sh[t][23] = rnorm[3 * e_my + 2];
    }
    __syncthreads();

    const int cnt = min(128, n_edges - base);

    // software-pipelined gathers
    int src_c = src_sh[0];
    int dst_c = dst_sh[0];
    const float* sp = g_spass + (size_t)dst_c * 384 + t;
    const float* vp = v_in + (size_t)dst_c * 384 + t;
    float sp0 = sp[0], sp1 = sp[128], sp2 = sp[256];
    float vv0 = vp[0], vv1 = vp[128], vv2 = vp[256];

    for (int e = 0; e < cnt; e++) {
        const int src = src_c;
        // prefetch next edge's gathers
        float nsp0 = 0.f, nsp1 = 0.f, nsp2 = 0.f, nvv0 = 0.f, nvv1 = 0.f, nvv2 = 0.f;
        if (e + 1 < cnt) {
            src_c = src_sh[e + 1];
            dst_c = dst_sh[e + 1];
            const float* spn = g_spass + (size_t)dst_c * 384 + t;
            const float* vpn = v_in + (size_t)dst_c * 384 + t;
            nsp0 = spn[0]; nsp1 = spn[128]; nsp2 = spn[256];
            nvv0 = vpn[0]; nvv1 = vpn[128]; nvv2 = vpn[256];
        }

        // dot products (smem broadcast + register weights) hide prefetch latency
        const float* row = rb_sh[e];
        unsigned long long a0 = 0ull, a1 = 0ull, a2 = 0ull;
        #pragma unroll
        for (int p = 0; p < 5; p++) {
            ulonglong2 rp = ((const ulonglong2*)row)[p];
            a0 = fma2(rp.x, wrP0[2 * p], a0);
            a0 = fma2(rp.y, wrP0[2 * p + 1], a0);
            a1 = fma2(rp.x, wrP1[2 * p], a1);
            a1 = fma2(rp.y, wrP1[2 * p + 1], a1);
            a2 = fma2(rp.x, wrP2[2 * p], a2);
            a2 = fma2(rp.y, wrP2[2 * p + 1], a2);
        }
        const float fc  = row[20];
        const float rn0 = row[21], rn1 = row[22], rn2 = row[23];

        float g   = (lof(a0) + hif(a0) + br0) * fc * sp0;
        float ds  = (lof(a1) + hif(a1) + br1) * fc * sp1;
        float rep = (lof(a2) + hif(a2) + br2) * fc * sp2;

        atomicAdd(s_out + (size_t)src * 128 + t, ds);

        float* vo = v_out + (size_t)src * 384 + t;
        atomicAdd(vo,       fmaf(vv0, g, rn0 * rep));
        atomicAdd(vo + 128, fmaf(vv1, g, rn1 * rep));
        atomicAdd(vo + 256, fmaf(vv2, g, rn2 * rep));

        sp0 = nsp0; sp1 = nsp1; sp2 = nsp2;
        vv0 = nvv0; vv1 = nvv1; vv2 = nvv2;
    }
}

// ---------- launch ----------
extern "C" void kernel_launch(void* const* d_in, const int* in_sizes, int n_in,
                              void* d_out, int out_size)
{
    const float* s     = (const float*)d_in[0];
    const float* v     = (const float*)d_in[1];
    const int*   edges = (const int*)d_in[2];
    const float* r_ij  = (const float*)d_in[3];
    const float* rnorm = (const float*)d_in[4];
    const float* W1    = (const float*)d_in[5];
    const float* b1    = (const float*)d_in[6];
    const float* W2    = (const float*)d_in[7];
    const float* b2    = (const float*)d_in[8];
    const float* Wr    = (const float*)d_in[9];
    const float* br    = (const float*)d_in[10];

    const int n_nodes = in_sizes[0] / EMB;
    const int n_edges = in_sizes[2] / 2;

    float* s_out = (float*)d_out;
    float* v_out = s_out + (size_t)n_nodes * EMB;

    // init outputs: s_out = s, v_out = v (capturable async D2D copies)
    cudaMemcpyAsync(s_out, s, (size_t)n_nodes * EMB * sizeof(float),
                    cudaMemcpyDeviceToDevice, 0);
    cudaMemcpyAsync(v_out, v, (size_t)n_nodes * 3 * EMB * sizeof(float),
                    cudaMemcpyDeviceToDevice, 0);

    // opt-in to ~99KB dynamic smem (idempotent, not a stream op)
    static int smem_set = 0;
    if (!smem_set) {
        cudaFuncSetAttribute(gemm1_kernel,
            cudaFuncAttributeMaxDynamicSharedMemorySize, GEMM_SMEM_BYTES);
        cudaFuncSetAttribute(gemm2_kernel,
            cudaFuncAttributeMaxDynamicSharedMemorySize, GEMM_SMEM_BYTES);
        smem_set = 1;
    }

    const int gemm_grid = 296;  // 2 blocks/SM x 148 SMs, grid-stride inside
    gemm1_kernel<<<gemm_grid, 128, GEMM_SMEM_BYTES>>>(s, W1, b1, n_nodes);
    gemm2_kernel<<<gemm_grid, 128, GEMM_SMEM_BYTES>>>(W2, b2, n_nodes);

    const int edge_blocks = (n_edges + 127) / 128;
    edge_kernel<<<edge_blocks, 128>>>(edges, r_ij, rnorm, Wr, br,
                                      v, s_out, v_out, n_edges);
}

// round 5
// speedup vs baseline: 1.3015x; 1.0428x over previous
#include <cuda_runtime.h>
#include <cstdint>

#define N_NODES 50000
#define EMB 128
#define NRBF 20

// Scratch (static device arrays are allowed; runtime alloc is not)
__device__ float g_h[(size_t)N_NODES * EMB];         // silu(s@W1+b1)
__device__ float g_spass[(size_t)N_NODES * 3 * EMB]; // h@W2+b2

// ---------- f32x2 helpers ----------
__device__ __forceinline__ unsigned long long fma2(unsigned long long a,
                                                   unsigned long long b,
                                                   unsigned long long c) {
    unsigned long long d;
    asm("fma.rn.f32x2 %0, %1, %2, %3;" : "=l"(d) : "l"(a), "l"(b), "l"(c));
    return d;
}
__device__ __forceinline__ unsigned long long dup2(float a) {
    unsigned long long r;
    asm("mov.b64 %0, {%1, %1};" : "=l"(r) : "f"(a));
    return r;
}
__device__ __forceinline__ unsigned long long packf(float lo, float hi) {
    unsigned long long r;
    asm("mov.b64 %0, {%1, %2};" : "=l"(r) : "f"(lo), "f"(hi));
    return r;
}
__device__ __forceinline__ float lof(unsigned long long v) {
    return __uint_as_float((unsigned)(v & 0xffffffffull));
}
__device__ __forceinline__ float hif(unsigned long long v) {
    return __uint_as_float((unsigned)(v >> 32));
}

// ---------- 8x8 register-blocked GEMM, double-buffered inner loop ----------
// C[M x N] = act(A[M x 128] @ W[128 x N] + b)
// Block: 128 threads. Tile: 128 rows x 64-col chunks.
// Thread t: rg = t>>3 (16 rowgroups of 8 rows), cg = t&7 (8 colgroups of 8 cols).
#define AS_STRIDE 129
#define GEMM_SMEM_BYTES ((128 * AS_STRIDE + 128 * 64) * 4)

__device__ __forceinline__ void mac8(unsigned long long acc[8][4],
                                     const float a[8],
                                     ulonglong2 wA, ulonglong2 wB) {
    #pragma unroll
    for (int i = 0; i < 8; i++) {
        unsigned long long a2 = dup2(a[i]);
        acc[i][0] = fma2(a2, wA.x, acc[i][0]);
        acc[i][1] = fma2(a2, wA.y, acc[i][1]);
        acc[i][2] = fma2(a2, wB.x, acc[i][2]);
        acc[i][3] = fma2(a2, wB.y, acc[i][3]);
    }
}

template <int N, int ACT>
__device__ __forceinline__ void gemm8x8_body(
    const float* __restrict__ A, const float* __restrict__ W,
    const float* __restrict__ bias, float* __restrict__ C, int M)
{
    extern __shared__ __align__(16) float smem[];
    float* A_sh = smem;                    // 128 * 129
    float* W_sh = smem + 128 * AS_STRIDE;  // 128 * 64

    const int t = threadIdx.x;
    const int cg = t & 7;
    const int rg = t >> 3;

    for (int m0 = blockIdx.x * 128; m0 < M; m0 += gridDim.x * 128) {
        // ---- stage A tile (128 x 128): coalesced reads, conflict-free writes
        for (int lin = t; lin < 128 * 128; lin += 128) {
            int m = lin >> 7;
            int k = lin & 127;
            float val = (m0 + m < M) ? A[(size_t)(m0 + m) * 128 + k] : 0.f;
            A_sh[m * AS_STRIDE + k] = val;
        }
        __syncthreads();

        for (int n0 = 0; n0 < N; n0 += 64) {
            // ---- stage W chunk (128 x 64) as float4
            for (int idx = t; idx < 128 * 16; idx += 128) {
                int k = idx >> 4;
                int j = idx & 15;
                ((float4*)(W_sh + k * 64))[j] =
                    ((const float4*)(W + (size_t)k * N + n0))[j];
            }
            __syncthreads();

            unsigned long long acc[8][4];
            #pragma unroll
            for (int i = 0; i < 8; i++)
                #pragma unroll
                for (int j = 0; j < 4; j++) acc[i][j] = 0ull;

            const float* arow = A_sh + rg * 8 * AS_STRIDE;
            const float* wcol = W_sh + cg * 8;

            // ---- double-buffered k loop: loads for k+1 issue before FMAs of k
            float a[2][8];
            ulonglong2 wA[2], wB[2];
            #pragma unroll
            for (int i = 0; i < 8; i++) a[0][i] = arow[i * AS_STRIDE];
            wA[0] = *(const ulonglong2*)(wcol);
            wB[0] = *(const ulonglong2*)(wcol + 4);

            for (int k = 0; k < 128; k += 2) {
                const int k1 = k + 1;
                const int k2 = (k + 2) & 127;  // wraps at end; values unused

                wA[1] = *(const ulonglong2*)(wcol + k1 * 64);
                wB[1] = *(const ulonglong2*)(wcol + k1 * 64 + 4);
                #pragma unroll
                for (int i = 0; i < 8; i++) a[1][i] = arow[i * AS_STRIDE + k1];

                mac8(acc, a[0], wA[0], wB[0]);

                wA[0] = *(const ulonglong2*)(wcol + k2 * 64);
                wB[0] = *(const ulonglong2*)(wcol + k2 * 64 + 4);
                #pragma unroll
                for (int i = 0; i < 8; i++) a[0][i] = arow[i * AS_STRIDE + k2];

                mac8(acc, a[1], wA[1], wB[1]);
            }

            // ---- epilogue
            const int ncol = n0 + cg * 8;
            float bb[8];
            #pragma unroll
            for (int j = 0; j < 8; j++) bb[j] = bias[ncol + j];

            #pragma unroll
            for (int i = 0; i < 8; i++) {
                const int m = m0 + rg * 8 + i;
                if (m < M) {
                    float c[8];
                    #pragma unroll
                    for (int j = 0; j < 4; j++) {
                        c[2 * j]     = lof(acc[i][j]) + bb[2 * j];
                        c[2 * j + 1] = hif(acc[i][j]) + bb[2 * j + 1];
                    }
                    if (ACT) {
                        #pragma unroll
                        for (int j = 0; j < 8; j++)
                            c[j] = c[j] / (1.0f + __expf(-c[j]));  // silu
                    }
                    float4* outp = (float4*)(C + (size_t)m * N + ncol);
                    outp[0] = make_float4(c[0], c[1], c[2], c[3]);
                    outp[1] = make_float4(c[4], c[5], c[6], c[7]);
                }
            }
            __syncthreads();  // protect W_sh (and A_sh before restage)
        }
    }
}

__global__ __launch_bounds__(128) void gemm1_kernel(
    const float* __restrict__ A, const float* __restrict__ W,
    const float* __restrict__ bias, int M)
{
    gemm8x8_body<128, 1>(A, W, bias, g_h, M);
}

__global__ __launch_bounds__(128) void gemm2_kernel(
    const float* __restrict__ W, const float* __restrict__ bias, int M)
{
    gemm8x8_body<384, 0>(g_h, W, bias, g_spass, M);
}

// ---------- Edge kernel ----------
// block: 128 threads, one chunk of 128 edges per block.
// thread t owns output columns t (delta_v_g), t+128 (delta_s), t+256 (delta_rep).
__global__ __launch_bounds__(128) void edge_kernel(
    const int* __restrict__ edges,         // [E][2] int32 pairs
    const float* __restrict__ r_ij,        // [E]
    const float* __restrict__ rnorm,       // [E][3]
    const float* __restrict__ Wr,          // [20][384]
    const float* __restrict__ br,          // [384]
    const float* __restrict__ v_in,        // [N][3][128]
    float* __restrict__ s_out,             // [N][128]
    float* __restrict__ v_out,             // [N][3][128]
    int n_edges)
{
    __shared__ __align__(16) float rb_sh[128][24];  // 20 rbf, fc, rn0..rn2
    __shared__ int src_sh[128];
    __shared__ int dst_sh[128];

    const int t = threadIdx.x;
    const int base = blockIdx.x * 128;

    // Preload Wr columns (packed pairs over n) + bias
    unsigned long long wrP0[10], wrP1[10], wrP2[10];
    #pragma unroll
    for (int p = 0; p < 10; p++) {
        wrP0[p] = packf(Wr[(2 * p) * 384 + t],       Wr[(2 * p + 1) * 384 + t]);
        wrP1[p] = packf(Wr[(2 * p) * 384 + 128 + t], Wr[(2 * p + 1) * 384 + 128 + t]);
        wrP2[p] = packf(Wr[(2 * p) * 384 + 256 + t], Wr[(2 * p + 1) * 384 + 256 + t]);
    }
    const float br0 = br[t], br1 = br[128 + t], br2 = br[256 + t];

    // Phase 1: thread t computes edge (base+t)'s rbf / fcut / geometry
    const int e_my = base + t;
    if (e_my < n_edges) {
        int2 ed = ((const int2*)edges)[e_my];
        src_sh[t] = ed.x;
        dst_sh[t] = ed.y;
        float r = r_ij[e_my];
        float inv_r = 1.0f / r;
        float q = r * 0.2f;  // r / R_CUT
        #pragma unroll
        for (int n = 1; n <= NRBF; n++) {
            rb_sh[t][n - 1] = sinpif((float)n * q) * inv_r;
        }
        float fc = (r <= 5.0f) ? 0.5f * (cospif(q) + 1.0f) : 0.0f;
        rb_sh[t][20] = fc;
        rb_sh[t][21] = rnorm[3 * e_my + 0];
        rb_sh[t][22] = rnorm[3 * e_my + 1];
        rb_sh[t][23] = rnorm[3 * e_my + 2];
    }
    __syncthreads();

    const int cnt = min(128, n_edges - base);

    // software-pipelined gathers
    int src_c = src_sh[0];
    int dst_c = dst_sh[0];
    const float* sp = g_spass + (size_t)dst_c * 384 + t;
    const float* vp = v_in + (size_t)dst_c * 384 + t;
    float sp0 = sp[0], sp1 = sp[128], sp2 = sp[256];
    float vv0 = vp[0], vv1 = vp[128], vv2 = vp[256];

    for (int e = 0; e < cnt; e++) {
        const int src = src_c;
        // prefetch next edge's gathers
        float nsp0 = 0.f, nsp1 = 0.f, nsp2 = 0.f, nvv0 = 0.f, nvv1 = 0.f, nvv2 = 0.f;
        if (e + 1 < cnt) {
            src_c = src_sh[e + 1];
            dst_c = dst_sh[e + 1];
            const float* spn = g_spass + (size_t)dst_c * 384 + t;
            const float* vpn = v_in + (size_t)dst_c * 384 + t;
            nsp0 = spn[0]; nsp1 = spn[128]; nsp2 = spn[256];
            nvv0 = vpn[0]; nvv1 = vpn[128]; nvv2 = vpn[256];
        }

        // dot products (smem broadcast + register weights) hide prefetch latency
        const float* row = rb_sh[e];
        unsigned long long a0 = 0ull, a1 = 0ull, a2 = 0ull;
        #pragma unroll
        for (int p = 0; p < 5; p++) {
            ulonglong2 rp = ((const ulonglong2*)row)[p];
            a0 = fma2(rp.x, wrP0[2 * p], a0);
            a0 = fma2(rp.y, wrP0[2 * p + 1], a0);
            a1 = fma2(rp.x, wrP1[2 * p], a1);
            a1 = fma2(rp.y, wrP1[2 * p + 1], a1);
            a2 = fma2(rp.x, wrP2[2 * p], a2);
            a2 = fma2(rp.y, wrP2[2 * p + 1], a2);
        }
        const float fc  = row[20];
        const float rn0 = row[21], rn1 = row[22], rn2 = row[23];

        float g   = (lof(a0) + hif(a0) + br0) * fc * sp0;
        float ds  = (lof(a1) + hif(a1) + br1) * fc * sp1;
        float rep = (lof(a2) + hif(a2) + br2) * fc * sp2;

        atomicAdd(s_out + (size_t)src * 128 + t, ds);

        float* vo = v_out + (size_t)src * 384 + t;
        atomicAdd(vo,       fmaf(vv0, g, rn0 * rep));
        atomicAdd(vo + 128, fmaf(vv1, g, rn1 * rep));
        atomicAdd(vo + 256, fmaf(vv2, g, rn2 * rep));

        sp0 = nsp0; sp1 = nsp1; sp2 = nsp2;
        vv0 = nvv0; vv1 = nvv1; vv2 = nvv2;
    }
}

// ---------- launch ----------
extern "C" void kernel_launch(void* const* d_in, const int* in_sizes, int n_in,
                              void* d_out, int out_size)
{
    const float* s     = (const float*)d_in[0];
    const float* v     = (const float*)d_in[1];
    const int*   edges = (const int*)d_in[2];
    const float* r_ij  = (const float*)d_in[3];
    const float* rnorm = (const float*)d_in[4];
    const float* W1    = (const float*)d_in[5];
    const float* b1    = (const float*)d_in[6];
    const float* W2    = (const float*)d_in[7];
    const float* b2    = (const float*)d_in[8];
    const float* Wr    = (const float*)d_in[9];
    const float* br    = (const float*)d_in[10];

    const int n_nodes = in_sizes[0] / EMB;
    const int n_edges = in_sizes[2] / 2;

    float* s_out = (float*)d_out;
    float* v_out = s_out + (size_t)n_nodes * EMB;

    // one-time host-side resource setup (no device memory involved)
    static cudaStream_t s2 = nullptr;
    static cudaEvent_t ev_fork = nullptr, ev_join = nullptr;
    if (!s2) {
        cudaStreamCreateWithFlags(&s2, cudaStreamNonBlocking);
        cudaEventCreateWithFlags(&ev_fork, cudaEventDisableTiming);
        cudaEventCreateWithFlags(&ev_join, cudaEventDisableTiming);
        cudaFuncSetAttribute(gemm1_kernel,
            cudaFuncAttributeMaxDynamicSharedMemorySize, GEMM_SMEM_BYTES);
        cudaFuncSetAttribute(gemm2_kernel,
            cudaFuncAttributeMaxDynamicSharedMemorySize, GEMM_SMEM_BYTES);
    }

    // fork: output-init copies run on side stream, overlapped with GEMMs
    cudaEventRecord(ev_fork, 0);
    cudaStreamWaitEvent(s2, ev_fork, 0);
    cudaMemcpyAsync(s_out, s, (size_t)n_nodes * EMB * sizeof(float),
                    cudaMemcpyDeviceToDevice, s2);
    cudaMemcpyAsync(v_out, v, (size_t)n_nodes * 3 * EMB * sizeof(float),
                    cudaMemcpyDeviceToDevice, s2);
    cudaEventRecord(ev_join, s2);

    const int gemm_grid = 296;  // 2 blocks/SM x 148 SMs, grid-stride inside
    gemm1_kernel<<<gemm_grid, 128, GEMM_SMEM_BYTES>>>(s, W1, b1, n_nodes);
    gemm2_kernel<<<gemm_grid, 128, GEMM_SMEM_BYTES>>>(W2, b2, n_nodes);

    // join: edge kernel needs initialized outputs + g_spass
    cudaStreamWaitEvent(0, ev_join, 0);
    const int edge_blocks = (n_edges + 127) / 128;
    edge_kernel<<<edge_blocks, 128>>>(edges, r_ij, rnorm, Wr, br,
                                      v, s_out, v_out, n_edges);
}